// round 12
// baseline (speedup 1.0000x reference)
#include <cuda_runtime.h>
#include <cuda_bf16.h>
#include <cstdint>

// ---------------------------------------------------------------------------
// SlotAttention restructured:
//   logits[b,n,s] = LN(x)[b,n,:] . qt[b,s,:]      (qt = scale*log2e * Wk^T q)
//   acc[b,s,:]    = sum_n p[b,n,s] * LN(x)[b,n,:] ,  psum[b,s] = sum_n p
//   updates       = (acc @ Wv^T) / psum
// so k and v are never materialized; per-iteration traffic = one pass over x.
// ---------------------------------------------------------------------------

#define FULLMASK 0xffffffffu
#define CH   16            // chunks per batch (partial accumulators)
#define BN   128           // batches
#define SD   448           // S*D = 7*64
#define QTC  (0.125f * 1.4426950408889634f)   // D^-0.5 * log2(e)

using u64 = unsigned long long;

__device__ float g_slots[BN * SD];
__device__ float g_qt[BN * SD];
__device__ float g_acc_part[BN * CH * SD];
__device__ float g_psum_part[BN * CH * 8];

// ----------------------- packed f32x2 helpers (Blackwell) -------------------
__device__ __forceinline__ u64 f2pack(float lo, float hi) {
    u64 r; asm("mov.b64 %0,{%1,%2};" : "=l"(r) : "f"(lo), "f"(hi)); return r;
}
__device__ __forceinline__ void f2un(u64 v, float& a, float& b) {
    asm("mov.b64 {%0,%1},%2;" : "=f"(a), "=f"(b) : "l"(v));
}
__device__ __forceinline__ u64 f2fma(u64 a, u64 b, u64 c) {
    u64 d; asm("fma.rn.f32x2 %0,%1,%2,%3;" : "=l"(d) : "l"(a), "l"(b), "l"(c)); return d;
}
__device__ __forceinline__ u64 f2mul(u64 a, u64 b) {
    u64 d; asm("mul.rn.f32x2 %0,%1,%2;" : "=l"(d) : "l"(a), "l"(b)); return d;
}
__device__ __forceinline__ u64 f2add(u64 a, u64 b) {
    u64 d; asm("add.rn.f32x2 %0,%1,%2;" : "=l"(d) : "l"(a), "l"(b)); return d;
}
__device__ __forceinline__ float ex2f(float x) {
    float r; asm("ex2.approx.f32 %0,%1;" : "=f"(r) : "f"(x)); return r;
}
__device__ __forceinline__ float rcpf(float x) {
    float r; asm("rcp.approx.f32 %0,%1;" : "=f"(r) : "f"(x)); return r;
}
__device__ __forceinline__ float rsqf(float x) {
    float r; asm("rsqrt.approx.f32 %0,%1;" : "=f"(r) : "f"(x)); return r;
}
__device__ __forceinline__ float sigf(float x) { return rcpf(1.f + __expf(-x)); }

__device__ __forceinline__ float4 ldg4(const float* p) {
    return __ldg((const float4*)p);
}

// ===========================================================================
// Attention kernel: grid (CH, BN), block 128 (4 warps).
// 8 lanes per row, 4 rows per warp-pass. acc + qt register-resident.
// ===========================================================================
__global__ void __launch_bounds__(128)
attn_kernel(const float* __restrict__ inp,
            const float* __restrict__ lg,
            const float* __restrict__ lb)
{
    __shared__ __align__(16) float sbuf[4 * SD + 32];

    const int b = blockIdx.y, chunk = blockIdx.x;
    const int tid = threadIdx.x;
    const int warp = tid >> 5, lane = tid & 31;
    const int rowgrp = lane >> 3, dgrp = lane & 7;
    const int d0 = dgrp * 4, d1 = 32 + dgrp * 4;

    for (int i = tid; i < SD; i += 128) sbuf[i] = g_qt[b * SD + i];
    __syncthreads();

    u64 qt[7][4];
#pragma unroll
    for (int s = 0; s < 7; ++s) {
        float4 a = *(const float4*)&sbuf[s * 64 + d0];
        float4 c = *(const float4*)&sbuf[s * 64 + d1];
        qt[s][0] = f2pack(a.x, a.y); qt[s][1] = f2pack(a.z, a.w);
        qt[s][2] = f2pack(c.x, c.y); qt[s][3] = f2pack(c.z, c.w);
    }
    float4 ga = ldg4(lg + d0), gc = ldg4(lg + d1);
    float4 ba = ldg4(lb + d0), bc = ldg4(lb + d1);
    const u64 gp0 = f2pack(ga.x, ga.y), gp1 = f2pack(ga.z, ga.w);
    const u64 gp2 = f2pack(gc.x, gc.y), gp3 = f2pack(gc.z, gc.w);
    const u64 bp0 = f2pack(ba.x, ba.y), bp1 = f2pack(ba.z, ba.w);
    const u64 bp2 = f2pack(bc.x, bc.y), bp3 = f2pack(bc.z, bc.w);

    u64 acc[7][4];
    float psum[7];
    const u64 z2 = f2pack(0.f, 0.f);
#pragma unroll
    for (int s = 0; s < 7; ++s) {
        psum[s] = 0.f;
        acc[s][0] = z2; acc[s][1] = z2; acc[s][2] = z2; acc[s][3] = z2;
    }

    const int ROWS = 4096 / CH;      // 256
    const int NP = ROWS / 16;        // 16 passes, 16 rows/block-pass
    const float* rb = inp + ((size_t)b * 4096 + (size_t)chunk * ROWS) * 64;
    const int r0 = warp * 4 + rowgrp;

    const float* pa = rb + (size_t)r0 * 64 + d0;
    const float* pc = rb + (size_t)r0 * 64 + d1;
    float4 xa = ldg4(pa);
    float4 xc = ldg4(pc);
    float4 na = xa, nc = xc;

#pragma unroll 1
    for (int pass = 0; pass < NP; ++pass) {
        pa += 16 * 64; pc += 16 * 64;
        if (pass + 1 < NP) {
            na = ldg4(pa);
            nc = ldg4(pc);
        }
        // ---- LN stats over the 8-lane group ----
        float sum = ((xa.x + xa.y) + (xa.z + xa.w)) + ((xc.x + xc.y) + (xc.z + xc.w));
        float ssq = fmaf(xa.x, xa.x, fmaf(xa.y, xa.y, fmaf(xa.z, xa.z, xa.w * xa.w)))
                  + fmaf(xc.x, xc.x, fmaf(xc.y, xc.y, fmaf(xc.z, xc.z, xc.w * xc.w)));
        sum += __shfl_xor_sync(FULLMASK, sum, 1);
        ssq += __shfl_xor_sync(FULLMASK, ssq, 1);
        sum += __shfl_xor_sync(FULLMASK, sum, 2);
        ssq += __shfl_xor_sync(FULLMASK, ssq, 2);
        sum += __shfl_xor_sync(FULLMASK, sum, 4);
        ssq += __shfl_xor_sync(FULLMASK, ssq, 4);
        float mu = sum * 0.015625f;
        float var = fmaf(ssq, 0.015625f, -mu * mu);
        float rs = rsqf(var + 1e-5f);
        u64 mmu = f2pack(-mu, -mu), rsp = f2pack(rs, rs);
        u64 xn0 = f2fma(f2mul(f2add(f2pack(xa.x, xa.y), mmu), rsp), gp0, bp0);
        u64 xn1 = f2fma(f2mul(f2add(f2pack(xa.z, xa.w), mmu), rsp), gp1, bp1);
        u64 xn2 = f2fma(f2mul(f2add(f2pack(xc.x, xc.y), mmu), rsp), gp2, bp2);
        u64 xn3 = f2fma(f2mul(f2add(f2pack(xc.z, xc.w), mmu), rsp), gp3, bp3);
        // ---- logits ----
        float l[7];
#pragma unroll
        for (int s = 0; s < 7; ++s) {
            u64 t = f2mul(xn0, qt[s][0]);
            t = f2fma(xn1, qt[s][1], t);
            t = f2fma(xn2, qt[s][2], t);
            t = f2fma(xn3, qt[s][3], t);
            float lo, hi; f2un(t, lo, hi);
            l[s] = lo + hi;
        }
#pragma unroll
        for (int s = 0; s < 7; ++s) l[s] += __shfl_xor_sync(FULLMASK, l[s], 1);
#pragma unroll
        for (int s = 0; s < 7; ++s) l[s] += __shfl_xor_sync(FULLMASK, l[s], 2);
#pragma unroll
        for (int s = 0; s < 7; ++s) l[s] += __shfl_xor_sync(FULLMASK, l[s], 4);
        // ---- softmax over 7 slots (+EPS) ----
        float mx = l[0];
#pragma unroll
        for (int s = 1; s < 7; ++s) mx = fmaxf(mx, l[s]);
        float e[7]; float sump = 0.f;
#pragma unroll
        for (int s = 0; s < 7; ++s) { e[s] = ex2f(l[s] - mx); sump += e[s]; }
        float rinv = rcpf(sump);
#pragma unroll
        for (int s = 0; s < 7; ++s) {
            float p = fmaf(e[s], rinv, 1e-8f);
            psum[s] += p;
            u64 pp = f2pack(p, p);
            acc[s][0] = f2fma(pp, xn0, acc[s][0]);
            acc[s][1] = f2fma(pp, xn1, acc[s][1]);
            acc[s][2] = f2fma(pp, xn2, acc[s][2]);
            acc[s][3] = f2fma(pp, xn3, acc[s][3]);
        }
        xa = na; xc = nc;
    }

    __syncthreads();   // everyone done reading qt staging region of sbuf

    // ---- reduce across the 4 row-groups, stash per-warp results in shared ----
#pragma unroll
    for (int s = 0; s < 7; ++s) {
#pragma unroll
        for (int j = 0; j < 4; ++j) {
            float a0, a1; f2un(acc[s][j], a0, a1);
            a0 += __shfl_xor_sync(FULLMASK, a0, 8);
            a1 += __shfl_xor_sync(FULLMASK, a1, 8);
            a0 += __shfl_xor_sync(FULLMASK, a0, 16);
            a1 += __shfl_xor_sync(FULLMASK, a1, 16);
            if (lane < 8) {
                int dd = (j < 2) ? (d0 + j * 2) : (d1 + (j - 2) * 2);
                sbuf[warp * SD + s * 64 + dd]     = a0;
                sbuf[warp * SD + s * 64 + dd + 1] = a1;
            }
        }
        float ps = psum[s];
        ps += __shfl_xor_sync(FULLMASK, ps, 1);
        ps += __shfl_xor_sync(FULLMASK, ps, 2);
        ps += __shfl_xor_sync(FULLMASK, ps, 4);
        ps += __shfl_xor_sync(FULLMASK, ps, 8);
        ps += __shfl_xor_sync(FULLMASK, ps, 16);
        if (lane == 0) sbuf[4 * SD + warp * 8 + s] = ps;
    }
    __syncthreads();

    const int pi = b * CH + chunk;
    for (int i = tid; i < SD; i += 128)
        g_acc_part[pi * SD + i] = (sbuf[i] + sbuf[SD + i]) + (sbuf[2 * SD + i] + sbuf[3 * SD + i]);
    if (tid < 7)
        g_psum_part[pi * 8 + tid] =
            ((sbuf[4 * SD + tid] + sbuf[4 * SD + 8 + tid]) +
             (sbuf[4 * SD + 16 + tid] + sbuf[4 * SD + 24 + tid])) * 0.125f;  // 8x lane duplication
}

// ===========================================================================
// 8-lane-group dot helpers (coalesced weight-row reads, 7 slots amortized)
// ===========================================================================
__device__ __forceinline__ void gd7(const float* __restrict__ wrow,
                                    const float* __restrict__ vec,  // shared, stride 64
                                    int dgrp, float out[7])
{
    const int d0 = dgrp * 4, d1 = 32 + dgrp * 4;
    float4 wa = ldg4(wrow + d0);
    float4 wb = ldg4(wrow + d1);
#pragma unroll
    for (int s = 0; s < 7; ++s) {
        const float* v = vec + s * 64;
        float p = fmaf(wa.x, v[d0], fmaf(wa.y, v[d0 + 1], fmaf(wa.z, v[d0 + 2], wa.w * v[d0 + 3])))
                + fmaf(wb.x, v[d1], fmaf(wb.y, v[d1 + 1], fmaf(wb.z, v[d1 + 2], wb.w * v[d1 + 3])));
        p += __shfl_xor_sync(FULLMASK, p, 1);
        p += __shfl_xor_sync(FULLMASK, p, 2);
        p += __shfl_xor_sync(FULLMASK, p, 4);
        out[s] = p;
    }
}

__device__ __forceinline__ void gd7_128(const float* __restrict__ wrow,
                                        const float* __restrict__ vec,  // shared, stride 128
                                        int dgrp, float out[7])
{
    const int j0 = dgrp * 16;
    float4 w0 = ldg4(wrow + j0);
    float4 w1 = ldg4(wrow + j0 + 4);
    float4 w2 = ldg4(wrow + j0 + 8);
    float4 w3 = ldg4(wrow + j0 + 12);
#pragma unroll
    for (int s = 0; s < 7; ++s) {
        const float* v = vec + s * 128 + j0;
        float p = fmaf(w0.x, v[0],  fmaf(w0.y, v[1],  fmaf(w0.z, v[2],  w0.w * v[3])))
                + fmaf(w1.x, v[4],  fmaf(w1.y, v[5],  fmaf(w1.z, v[6],  w1.w * v[7])))
                + fmaf(w2.x, v[8],  fmaf(w2.y, v[9],  fmaf(w2.z, v[10], w2.w * v[11])))
                + fmaf(w3.x, v[12], fmaf(w3.y, v[13], fmaf(w3.z, v[14], w3.w * v[15])));
        p += __shfl_xor_sync(FULLMASK, p, 1);
        p += __shfl_xor_sync(FULLMASK, p, 2);
        p += __shfl_xor_sync(FULLMASK, p, 4);
        out[s] = p;
    }
}

// warp-per-slot LayerNorm of 7 rows of 64 in shared memory
__device__ __forceinline__ void ln7(const float* __restrict__ src, float* __restrict__ dst,
                                    const float* __restrict__ g, const float* __restrict__ bta,
                                    int warp, int lane)
{
    if (warp < 7) {
        float a = src[warp * 64 + lane], c = src[warp * 64 + 32 + lane];
        float s1 = a + c, s2 = fmaf(a, a, c * c);
#pragma unroll
        for (int off = 16; off >= 1; off >>= 1) {
            s1 += __shfl_xor_sync(FULLMASK, s1, off);
            s2 += __shfl_xor_sync(FULLMASK, s2, off);
        }
        float mu = s1 * 0.015625f;
        float var = fmaf(s2, 0.015625f, -mu * mu);
        float rs = rsqf(var + 1e-5f);
        dst[warp * 64 + lane]      = fmaf((a - mu) * rs, g[lane],      bta[lane]);
        dst[warp * 64 + 32 + lane] = fmaf((c - mu) * rs, g[32 + lane], bta[32 + lane]);
    }
}

// q = LN(slots) @ Wq^T ; qt = QTC * Wk^T q   (sln: shared normalized slots)
__device__ __forceinline__ void qt_phase(int b, int tid, int warp, int rowgrp, int dgrp,
                                         const float* __restrict__ sln, float* __restrict__ q_s,
                                         const float* __restrict__ Wq, const float* __restrict__ Wk)
{
    for (int rbv = warp * 4; rbv < 64; rbv += 32) {
        int e = rbv + rowgrp;
        float o7[7];
        gd7(Wq + e * 64, sln, dgrp, o7);
        if (dgrp == 0) {
#pragma unroll
            for (int s = 0; s < 7; ++s) q_s[s * 64 + e] = o7[s];
        }
    }
    __syncthreads();
    for (int o = tid; o < SD; o += 256) {
        int s = o >> 6, d = o & 63;
        const float* q = q_s + s * 64;
        float a0 = 0.f, a1 = 0.f, a2 = 0.f, a3 = 0.f;
#pragma unroll
        for (int e = 0; e < 64; e += 4) {
            a0 = fmaf(Wk[e * 64 + d],       q[e],     a0);
            a1 = fmaf(Wk[(e + 1) * 64 + d], q[e + 1], a1);
            a2 = fmaf(Wk[(e + 2) * 64 + d], q[e + 2], a2);
            a3 = fmaf(Wk[(e + 3) * 64 + d], q[e + 3], a3);
        }
        g_qt[b * SD + o] = QTC * ((a0 + a1) + (a2 + a3));
    }
}

// ===========================================================================
// Per-batch update: Wv projection, GRU, LN+MLP, new slots, next qt.
// grid 128 x 256 threads.
// ===========================================================================
__global__ void __launch_bounds__(256)
update_kernel(const float* __restrict__ Wv,
              const float* __restrict__ W_ih, const float* __restrict__ W_hh,
              const float* __restrict__ b_ih, const float* __restrict__ b_hh,
              const float* __restrict__ lmg, const float* __restrict__ lmb,
              const float* __restrict__ w1,  const float* __restrict__ b1,
              const float* __restrict__ w2,  const float* __restrict__ b2,
              const float* __restrict__ lsg, const float* __restrict__ lsb,
              const float* __restrict__ Wq,  const float* __restrict__ Wk,
              float* __restrict__ out)
{
    __shared__ float acc_s[SD], hprev_s[SD], upd_s[SD];
    __shared__ float gi_s[1344], gh_s[1344];
    __shared__ float h_s[SD], mx_s[SD], m1_s[896], slot_s[SD], q_s[SD], psr[8];

    const int b = blockIdx.x, tid = threadIdx.x;
    const int warp = tid >> 5, lane = tid & 31;
    const int rowgrp = lane >> 3, dgrp = lane & 7;

    // ---- A: sum chunk partials; load previous slots ----
    for (int i = tid; i < SD; i += 256) {
        float ssum = 0.f;
#pragma unroll
        for (int ch = 0; ch < CH; ++ch) ssum += __ldg(&g_acc_part[(b * CH + ch) * SD + i]);
        acc_s[i] = ssum;
        hprev_s[i] = g_slots[b * SD + i];
    }
    if (tid < 7) {
        float ssum = 0.f;
#pragma unroll
        for (int ch = 0; ch < CH; ++ch) ssum += __ldg(&g_psum_part[(b * CH + ch) * 8 + tid]);
        psr[tid] = 1.f / ssum;
    }
    __syncthreads();

    // ---- B: updates = (acc @ Wv^T) / psum ----
    for (int rbv = warp * 4; rbv < 64; rbv += 32) {
        int e = rbv + rowgrp;
        float o7[7];
        gd7(Wv + e * 64, acc_s, dgrp, o7);
        if (dgrp == 0) {
#pragma unroll
            for (int s = 0; s < 7; ++s) upd_s[s * 64 + e] = o7[s] * psr[s];
        }
    }
    __syncthreads();

    // ---- C: GRU gate pre-activations ----
    for (int rbv = warp * 4; rbv < 384; rbv += 32) {
        int row = rbv + rowgrp;
        bool ih = row < 192;
        int k = ih ? row : row - 192;
        const float* w = (ih ? W_ih : W_hh) + k * 64;
        const float* v = ih ? upd_s : hprev_s;
        float o7[7];
        gd7(w, v, dgrp, o7);
        if (dgrp == 0) {
            float* dst = ih ? gi_s : gh_s;
#pragma unroll
            for (int s = 0; s < 7; ++s) dst[s * 192 + k] = o7[s];
        }
    }
    __syncthreads();

    // ---- GRU gates ----
    for (int o = tid; o < SD; o += 256) {
        int s = o >> 6, d = o & 63;
        int base = s * 192 + d;
        float r = sigf((gi_s[base]       + b_ih[d])       + (gh_s[base]       + b_hh[d]));
        float z = sigf((gi_s[base + 64]  + b_ih[64 + d])  + (gh_s[base + 64]  + b_hh[64 + d]));
        float n = tanhf((gi_s[base + 128] + b_ih[128 + d]) + r * (gh_s[base + 128] + b_hh[128 + d]));
        h_s[o] = (1.f - z) * n + z * hprev_s[o];
    }
    __syncthreads();

    // ---- D: LN(h) with ln_mlp ----
    ln7(h_s, mx_s, lmg, lmb, warp, lane);
    __syncthreads();

    // ---- E: m1 = relu(mx @ w1^T + b1) ----
    for (int rbv = warp * 4; rbv < 128; rbv += 32) {
        int j = rbv + rowgrp;
        float o7[7];
        gd7(w1 + j * 64, mx_s, dgrp, o7);
        if (dgrp == 0) {
#pragma unroll
            for (int s = 0; s < 7; ++s) m1_s[s * 128 + j] = fmaxf(o7[s] + b1[j], 0.f);
        }
    }
    __syncthreads();

    // ---- F: slots = h + m1 @ w2^T + b2 ----
    for (int rbv = warp * 4; rbv < 64; rbv += 32) {
        int d = rbv + rowgrp;
        float o7[7];
        gd7_128(w2 + d * 128, m1_s, dgrp, o7);
        if (dgrp == 0) {
#pragma unroll
            for (int s = 0; s < 7; ++s) {
                float val = h_s[s * 64 + d] + o7[s] + b2[d];
                slot_s[s * 64 + d] = val;
                g_slots[b * SD + s * 64 + d] = val;
                out[b * SD + s * 64 + d] = val;
            }
        }
    }
    __syncthreads();

    // ---- G: next-iteration qt ----
    ln7(slot_s, mx_s, lsg, lsb, warp, lane);
    __syncthreads();
    qt_phase(b, tid, warp, rowgrp, dgrp, mx_s, q_s, Wq, Wk);
}

// ===========================================================================
// Slot init (reparameterized sampling) and initial qt.
// ===========================================================================
__global__ void __launch_bounds__(64)
init_slots_kernel(const float* __restrict__ nbg, const float* __restrict__ nfg,
                  const float* __restrict__ bgmu, const float* __restrict__ bgls,
                  const float* __restrict__ mu,   const float* __restrict__ ls)
{
    int b = blockIdx.x, d = threadIdx.x;
    g_slots[b * SD + d] = bgmu[d] + expf(bgls[d]) * nbg[b * 64 + d];
#pragma unroll
    for (int s = 1; s < 7; ++s)
        g_slots[b * SD + s * 64 + d] = mu[d] + expf(ls[d]) * nfg[(b * 6 + s - 1) * 64 + d];
}

__global__ void __launch_bounds__(256)
qt_kernel(const float* __restrict__ lsg, const float* __restrict__ lsb,
          const float* __restrict__ Wq, const float* __restrict__ Wk)
{
    __shared__ float slot_s[SD], sln_s[SD], q_s[SD];
    const int b = blockIdx.x, tid = threadIdx.x;
    const int warp = tid >> 5, lane = tid & 31;
    const int rowgrp = lane >> 3, dgrp = lane & 7;

    for (int i = tid; i < SD; i += 256) slot_s[i] = g_slots[b * SD + i];
    __syncthreads();
    ln7(slot_s, sln_s, lsg, lsb, warp, lane);
    __syncthreads();
    qt_phase(b, tid, warp, rowgrp, dgrp, sln_s, q_s, Wq, Wk);
}

// ===========================================================================
extern "C" void kernel_launch(void* const* d_in, const int* in_sizes, int n_in,
                              void* d_out, int out_size)
{
    const float* inputs   = (const float*)d_in[0];
    const float* noise_bg = (const float*)d_in[1];
    const float* noise_fg = (const float*)d_in[2];
    const float* ln_in_g  = (const float*)d_in[3];
    const float* ln_in_b  = (const float*)d_in[4];
    const float* ln_sl_g  = (const float*)d_in[5];
    const float* ln_sl_b  = (const float*)d_in[6];
    const float* ln_ml_g  = (const float*)d_in[7];
    const float* ln_ml_b  = (const float*)d_in[8];
    const float* Wq       = (const float*)d_in[9];
    const float* Wk       = (const float*)d_in[10];
    const float* Wv       = (const float*)d_in[11];
    const float* W_ih     = (const float*)d_in[12];
    const float* W_hh     = (const float*)d_in[13];
    const float* b_ih     = (const float*)d_in[14];
    const float* b_hh     = (const float*)d_in[15];
    const float* mlp_w1   = (const float*)d_in[16];
    const float* mlp_b1   = (const float*)d_in[17];
    const float* mlp_w2   = (const float*)d_in[18];
    const float* mlp_b2   = (const float*)d_in[19];
    const float* s_bg_mu  = (const float*)d_in[20];
    const float* s_bg_ls  = (const float*)d_in[21];
    const float* s_mu     = (const float*)d_in[22];
    const float* s_ls     = (const float*)d_in[23];
    float* out = (float*)d_out;

    init_slots_kernel<<<BN, 64>>>(noise_bg, noise_fg, s_bg_mu, s_bg_ls, s_mu, s_ls);
    qt_kernel<<<BN, 256>>>(ln_sl_g, ln_sl_b, Wq, Wk);
    for (int it = 0; it < 3; ++it) {
        attn_kernel<<<dim3(CH, BN), 128>>>(inputs, ln_in_g, ln_in_b);
        update_kernel<<<BN, 256>>>(Wv, W_ih, W_hh, b_ih, b_hh,
                                   ln_ml_g, ln_ml_b, mlp_w1, mlp_b1, mlp_w2, mlp_b2,
                                   ln_sl_g, ln_sl_b, Wq, Wk, out);
    }
}

// round 16
// speedup vs baseline: 1.3483x; 1.3483x over previous
#include <cuda_runtime.h>
#include <cuda_bf16.h>
#include <cstdint>

// ---------------------------------------------------------------------------
// SlotAttention restructured:
//   logits[b,n,s] = LN(x)[b,n,:] . qt[b,s,:]      (qt = scale*log2e * Wk^T q)
//   acc[b,s,:]    = sum_n p[b,n,s] * LN(x)[b,n,:] ,  psum[b,s] = sum_n p
//   updates       = (acc @ Wv^T) / psum
// R13: occupancy push. attn: qt in shared (regs ~175 -> ~120, 4 CTAs/SM).
//      update/qt kernels: 512 threads (occ 12.5% -> 25%, phases halved).
// ---------------------------------------------------------------------------

#define FULLMASK 0xffffffffu
#define CH   16            // chunks per batch (partial accumulators)
#define BN   128           // batches
#define SD   448           // S*D = 7*64
#define NT   512           // threads for update/qt kernels
#define QTC  (0.125f * 1.4426950408889634f)   // D^-0.5 * log2(e)

using u64 = unsigned long long;

__device__ float g_slots[BN * SD];
__device__ float g_qt[BN * SD];
__device__ float g_acc_part[BN * CH * SD];
__device__ float g_psum_part[BN * CH * 8];

// ----------------------- packed f32x2 helpers (Blackwell) -------------------
__device__ __forceinline__ u64 f2pack(float lo, float hi) {
    u64 r; asm("mov.b64 %0,{%1,%2};" : "=l"(r) : "f"(lo), "f"(hi)); return r;
}
__device__ __forceinline__ void f2un(u64 v, float& a, float& b) {
    asm("mov.b64 {%0,%1},%2;" : "=f"(a), "=f"(b) : "l"(v));
}
__device__ __forceinline__ u64 f2fma(u64 a, u64 b, u64 c) {
    u64 d; asm("fma.rn.f32x2 %0,%1,%2,%3;" : "=l"(d) : "l"(a), "l"(b), "l"(c)); return d;
}
__device__ __forceinline__ u64 f2mul(u64 a, u64 b) {
    u64 d; asm("mul.rn.f32x2 %0,%1,%2;" : "=l"(d) : "l"(a), "l"(b)); return d;
}
__device__ __forceinline__ u64 f2add(u64 a, u64 b) {
    u64 d; asm("add.rn.f32x2 %0,%1,%2;" : "=l"(d) : "l"(a), "l"(b)); return d;
}
__device__ __forceinline__ float ex2f(float x) {
    float r; asm("ex2.approx.f32 %0,%1;" : "=f"(r) : "f"(x)); return r;
}
__device__ __forceinline__ float rcpf(float x) {
    float r; asm("rcp.approx.f32 %0,%1;" : "=f"(r) : "f"(x)); return r;
}
__device__ __forceinline__ float rsqf(float x) {
    float r; asm("rsqrt.approx.f32 %0,%1;" : "=f"(r) : "f"(x)); return r;
}
__device__ __forceinline__ float sigf(float x) { return rcpf(1.f + __expf(-x)); }

__device__ __forceinline__ float4 ldg4(const float* p) {
    return __ldg((const float4*)p);
}

// volatile shared v4 load: keeps qt reads inside the pass loop (no LICM->regs)
__device__ __forceinline__ void lds128v(float4& v, uint32_t addr) {
    asm volatile("ld.shared.v4.f32 {%0,%1,%2,%3}, [%4];"
                 : "=f"(v.x), "=f"(v.y), "=f"(v.z), "=f"(v.w) : "r"(addr));
}

// ===========================================================================
// Attention kernel: grid (CH, BN), block 128 (4 warps), 4 CTAs/SM.
// 8 lanes per row, 4 rows per warp-pass. acc register-resident, qt in shared.
// ===========================================================================
__global__ void __launch_bounds__(128, 4)
attn_kernel(const float* __restrict__ inp,
            const float* __restrict__ lg,
            const float* __restrict__ lb)
{
    __shared__ __align__(16) float sbuf[4 * SD + 32];

    const int b = blockIdx.y, chunk = blockIdx.x;
    const int tid = threadIdx.x;
    const int warp = tid >> 5, lane = tid & 31;
    const int rowgrp = lane >> 3, dgrp = lane & 7;
    const int d0 = dgrp * 4, d1 = 32 + dgrp * 4;

    for (int i = tid; i < SD; i += 128) sbuf[i] = g_qt[b * SD + i];
    __syncthreads();

    // shared addresses of this lane's qt slices (slot stride = 256 bytes)
    const uint32_t qta0 = (uint32_t)__cvta_generic_to_shared(&sbuf[d0]);
    const uint32_t qta1 = (uint32_t)__cvta_generic_to_shared(&sbuf[d1]);

    float4 ga = ldg4(lg + d0), gc = ldg4(lg + d1);
    float4 ba = ldg4(lb + d0), bc = ldg4(lb + d1);
    const u64 gp0 = f2pack(ga.x, ga.y), gp1 = f2pack(ga.z, ga.w);
    const u64 gp2 = f2pack(gc.x, gc.y), gp3 = f2pack(gc.z, gc.w);
    const u64 bp0 = f2pack(ba.x, ba.y), bp1 = f2pack(ba.z, ba.w);
    const u64 bp2 = f2pack(bc.x, bc.y), bp3 = f2pack(bc.z, bc.w);

    u64 acc[7][4];
    float psum[7];
    const u64 z2 = f2pack(0.f, 0.f);
#pragma unroll
    for (int s = 0; s < 7; ++s) {
        psum[s] = 0.f;
        acc[s][0] = z2; acc[s][1] = z2; acc[s][2] = z2; acc[s][3] = z2;
    }

    const int ROWS = 4096 / CH;      // 256
    const int NP = ROWS / 16;        // 16 passes, 16 rows/block-pass
    const float* rb = inp + ((size_t)b * 4096 + (size_t)chunk * ROWS) * 64;
    const int r0 = warp * 4 + rowgrp;

    const float* pa = rb + (size_t)r0 * 64 + d0;
    const float* pc = rb + (size_t)r0 * 64 + d1;
    float4 xa = ldg4(pa);
    float4 xc = ldg4(pc);
    float4 na = xa, nc = xc;

#pragma unroll 1
    for (int pass = 0; pass < NP; ++pass) {
        pa += 16 * 64; pc += 16 * 64;
        if (pass + 1 < NP) {
            na = ldg4(pa);
            nc = ldg4(pc);
        }
        // ---- LN stats over the 8-lane group ----
        float sum = ((xa.x + xa.y) + (xa.z + xa.w)) + ((xc.x + xc.y) + (xc.z + xc.w));
        float ssq = fmaf(xa.x, xa.x, fmaf(xa.y, xa.y, fmaf(xa.z, xa.z, xa.w * xa.w)))
                  + fmaf(xc.x, xc.x, fmaf(xc.y, xc.y, fmaf(xc.z, xc.z, xc.w * xc.w)));
        sum += __shfl_xor_sync(FULLMASK, sum, 1);
        ssq += __shfl_xor_sync(FULLMASK, ssq, 1);
        sum += __shfl_xor_sync(FULLMASK, sum, 2);
        ssq += __shfl_xor_sync(FULLMASK, ssq, 2);
        sum += __shfl_xor_sync(FULLMASK, sum, 4);
        ssq += __shfl_xor_sync(FULLMASK, ssq, 4);
        float mu = sum * 0.015625f;
        float var = fmaf(ssq, 0.015625f, -mu * mu);
        float rs = rsqf(var + 1e-5f);
        u64 mmu = f2pack(-mu, -mu), rsp = f2pack(rs, rs);
        u64 xn0 = f2fma(f2mul(f2add(f2pack(xa.x, xa.y), mmu), rsp), gp0, bp0);
        u64 xn1 = f2fma(f2mul(f2add(f2pack(xa.z, xa.w), mmu), rsp), gp1, bp1);
        u64 xn2 = f2fma(f2mul(f2add(f2pack(xc.x, xc.y), mmu), rsp), gp2, bp2);
        u64 xn3 = f2fma(f2mul(f2add(f2pack(xc.z, xc.w), mmu), rsp), gp3, bp3);
        // ---- logits (qt streamed from shared; broadcast across rowgroups) ----
        float l[7];
#pragma unroll
        for (int s = 0; s < 7; ++s) {
            float4 qa, qc;
            lds128v(qa, qta0 + s * 256);
            lds128v(qc, qta1 + s * 256);
            u64 t = f2mul(xn0, f2pack(qa.x, qa.y));
            t = f2fma(xn1, f2pack(qa.z, qa.w), t);
            t = f2fma(xn2, f2pack(qc.x, qc.y), t);
            t = f2fma(xn3, f2pack(qc.z, qc.w), t);
            float lo, hi; f2un(t, lo, hi);
            l[s] = lo + hi;
        }
#pragma unroll
        for (int s = 0; s < 7; ++s) l[s] += __shfl_xor_sync(FULLMASK, l[s], 1);
#pragma unroll
        for (int s = 0; s < 7; ++s) l[s] += __shfl_xor_sync(FULLMASK, l[s], 2);
#pragma unroll
        for (int s = 0; s < 7; ++s) l[s] += __shfl_xor_sync(FULLMASK, l[s], 4);
        // ---- softmax over 7 slots (+EPS) ----
        float mx = l[0];
#pragma unroll
        for (int s = 1; s < 7; ++s) mx = fmaxf(mx, l[s]);
        float e[7]; float sump = 0.f;
#pragma unroll
        for (int s = 0; s < 7; ++s) { e[s] = ex2f(l[s] - mx); sump += e[s]; }
        float rinv = rcpf(sump);
#pragma unroll
        for (int s = 0; s < 7; ++s) {
            float p = fmaf(e[s], rinv, 1e-8f);
            psum[s] += p;
            u64 pp = f2pack(p, p);
            acc[s][0] = f2fma(pp, xn0, acc[s][0]);
            acc[s][1] = f2fma(pp, xn1, acc[s][1]);
            acc[s][2] = f2fma(pp, xn2, acc[s][2]);
            acc[s][3] = f2fma(pp, xn3, acc[s][3]);
        }
        xa = na; xc = nc;
    }

    __syncthreads();   // everyone done reading qt region of sbuf

    // ---- reduce across the 4 row-groups, stash per-warp results in shared ----
#pragma unroll
    for (int s = 0; s < 7; ++s) {
#pragma unroll
        for (int j = 0; j < 4; ++j) {
            float a0, a1; f2un(acc[s][j], a0, a1);
            a0 += __shfl_xor_sync(FULLMASK, a0, 8);
            a1 += __shfl_xor_sync(FULLMASK, a1, 8);
            a0 += __shfl_xor_sync(FULLMASK, a0, 16);
            a1 += __shfl_xor_sync(FULLMASK, a1, 16);
            if (lane < 8) {
                int dd = (j < 2) ? (d0 + j * 2) : (d1 + (j - 2) * 2);
                sbuf[warp * SD + s * 64 + dd]     = a0;
                sbuf[warp * SD + s * 64 + dd + 1] = a1;
            }
        }
        float ps = psum[s];
        ps += __shfl_xor_sync(FULLMASK, ps, 1);
        ps += __shfl_xor_sync(FULLMASK, ps, 2);
        ps += __shfl_xor_sync(FULLMASK, ps, 4);
        ps += __shfl_xor_sync(FULLMASK, ps, 8);
        ps += __shfl_xor_sync(FULLMASK, ps, 16);
        if (lane == 0) sbuf[4 * SD + warp * 8 + s] = ps;
    }
    __syncthreads();

    const int pi = b * CH + chunk;
    for (int i = tid; i < SD; i += 128)
        g_acc_part[pi * SD + i] = (sbuf[i] + sbuf[SD + i]) + (sbuf[2 * SD + i] + sbuf[3 * SD + i]);
    if (tid < 7)
        g_psum_part[pi * 8 + tid] =
            ((sbuf[4 * SD + tid] + sbuf[4 * SD + 8 + tid]) +
             (sbuf[4 * SD + 16 + tid] + sbuf[4 * SD + 24 + tid])) * 0.125f;  // 8x lane duplication
}

// ===========================================================================
// 8-lane-group dot helpers (coalesced weight-row reads, 7 slots amortized)
// ===========================================================================
__device__ __forceinline__ void gd7(const float* __restrict__ wrow,
                                    const float* __restrict__ vec,  // shared, stride 64
                                    int dgrp, float out[7])
{
    const int d0 = dgrp * 4, d1 = 32 + dgrp * 4;
    float4 wa = ldg4(wrow + d0);
    float4 wb = ldg4(wrow + d1);
#pragma unroll
    for (int s = 0; s < 7; ++s) {
        const float* v = vec + s * 64;
        float p = fmaf(wa.x, v[d0], fmaf(wa.y, v[d0 + 1], fmaf(wa.z, v[d0 + 2], wa.w * v[d0 + 3])))
                + fmaf(wb.x, v[d1], fmaf(wb.y, v[d1 + 1], fmaf(wb.z, v[d1 + 2], wb.w * v[d1 + 3])));
        p += __shfl_xor_sync(FULLMASK, p, 1);
        p += __shfl_xor_sync(FULLMASK, p, 2);
        p += __shfl_xor_sync(FULLMASK, p, 4);
        out[s] = p;
    }
}

__device__ __forceinline__ void gd7_128(const float* __restrict__ wrow,
                                        const float* __restrict__ vec,  // shared, stride 128
                                        int dgrp, float out[7])
{
    const int j0 = dgrp * 16;
    float4 w0 = ldg4(wrow + j0);
    float4 w1 = ldg4(wrow + j0 + 4);
    float4 w2 = ldg4(wrow + j0 + 8);
    float4 w3 = ldg4(wrow + j0 + 12);
#pragma unroll
    for (int s = 0; s < 7; ++s) {
        const float* v = vec + s * 128 + j0;
        float p = fmaf(w0.x, v[0],  fmaf(w0.y, v[1],  fmaf(w0.z, v[2],  w0.w * v[3])))
                + fmaf(w1.x, v[4],  fmaf(w1.y, v[5],  fmaf(w1.z, v[6],  w1.w * v[7])))
                + fmaf(w2.x, v[8],  fmaf(w2.y, v[9],  fmaf(w2.z, v[10], w2.w * v[11])))
                + fmaf(w3.x, v[12], fmaf(w3.y, v[13], fmaf(w3.z, v[14], w3.w * v[15])));
        p += __shfl_xor_sync(FULLMASK, p, 1);
        p += __shfl_xor_sync(FULLMASK, p, 2);
        p += __shfl_xor_sync(FULLMASK, p, 4);
        out[s] = p;
    }
}

// warp-per-slot LayerNorm of 7 rows of 64 in shared memory
__device__ __forceinline__ void ln7(const float* __restrict__ src, float* __restrict__ dst,
                                    const float* __restrict__ g, const float* __restrict__ bta,
                                    int warp, int lane)
{
    if (warp < 7) {
        float a = src[warp * 64 + lane], c = src[warp * 64 + 32 + lane];
        float s1 = a + c, s2 = fmaf(a, a, c * c);
#pragma unroll
        for (int off = 16; off >= 1; off >>= 1) {
            s1 += __shfl_xor_sync(FULLMASK, s1, off);
            s2 += __shfl_xor_sync(FULLMASK, s2, off);
        }
        float mu = s1 * 0.015625f;
        float var = fmaf(s2, 0.015625f, -mu * mu);
        float rs = rsqf(var + 1e-5f);
        dst[warp * 64 + lane]      = fmaf((a - mu) * rs, g[lane],      bta[lane]);
        dst[warp * 64 + 32 + lane] = fmaf((c - mu) * rs, g[32 + lane], bta[32 + lane]);
    }
}

// q = LN(slots) @ Wq^T ; qt = QTC * Wk^T q   (sln: shared normalized slots)
// NT threads (16 warps): part1 covers 64 rows in one shot.
__device__ __forceinline__ void qt_phase(int b, int tid, int warp, int rowgrp, int dgrp,
                                         const float* __restrict__ sln, float* __restrict__ q_s,
                                         const float* __restrict__ Wq, const float* __restrict__ Wk)
{
    {
        int e = warp * 4 + rowgrp;   // 16 warps x 4 rowgroups = 64 rows
        float o7[7];
        gd7(Wq + e * 64, sln, dgrp, o7);
        if (dgrp == 0) {
#pragma unroll
            for (int s = 0; s < 7; ++s) q_s[s * 64 + e] = o7[s];
        }
    }
    __syncthreads();
    for (int o = tid; o < SD; o += NT) {
        int s = o >> 6, d = o & 63;
        const float* q = q_s + s * 64;
        float a0 = 0.f, a1 = 0.f, a2 = 0.f, a3 = 0.f;
#pragma unroll
        for (int e = 0; e < 64; e += 4) {
            a0 = fmaf(Wk[e * 64 + d],       q[e],     a0);
            a1 = fmaf(Wk[(e + 1) * 64 + d], q[e + 1], a1);
            a2 = fmaf(Wk[(e + 2) * 64 + d], q[e + 2], a2);
            a3 = fmaf(Wk[(e + 3) * 64 + d], q[e + 3], a3);
        }
        g_qt[b * SD + o] = QTC * ((a0 + a1) + (a2 + a3));
    }
}

// ===========================================================================
// Per-batch update: Wv projection, GRU, LN+MLP, new slots, next qt.
// grid 128 x NT(512) threads, 16 warps.
// ===========================================================================
__global__ void __launch_bounds__(NT)
update_kernel(const float* __restrict__ Wv,
              const float* __restrict__ W_ih, const float* __restrict__ W_hh,
              const float* __restrict__ b_ih, const float* __restrict__ b_hh,
              const float* __restrict__ lmg, const float* __restrict__ lmb,
              const float* __restrict__ w1,  const float* __restrict__ b1,
              const float* __restrict__ w2,  const float* __restrict__ b2,
              const float* __restrict__ lsg, const float* __restrict__ lsb,
              const float* __restrict__ Wq,  const float* __restrict__ Wk,
              float* __restrict__ out)
{
    __shared__ float acc_s[SD], hprev_s[SD], upd_s[SD];
    __shared__ float gi_s[1344], gh_s[1344];
    __shared__ float h_s[SD], mx_s[SD], m1_s[896], slot_s[SD], q_s[SD], psr[8];

    const int b = blockIdx.x, tid = threadIdx.x;
    const int warp = tid >> 5, lane = tid & 31;
    const int rowgrp = lane >> 3, dgrp = lane & 7;

    // ---- A: sum chunk partials; load previous slots ----
    for (int i = tid; i < SD; i += NT) {
        float ssum = 0.f;
#pragma unroll
        for (int ch = 0; ch < CH; ++ch) ssum += __ldg(&g_acc_part[(b * CH + ch) * SD + i]);
        acc_s[i] = ssum;
        hprev_s[i] = g_slots[b * SD + i];
    }
    if (tid < 7) {
        float ssum = 0.f;
#pragma unroll
        for (int ch = 0; ch < CH; ++ch) ssum += __ldg(&g_psum_part[(b * CH + ch) * 8 + tid]);
        psr[tid] = 1.f / ssum;
    }
    __syncthreads();

    // ---- B: updates = (acc @ Wv^T) / psum  (64 rows, one shot) ----
    {
        int e = warp * 4 + rowgrp;
        float o7[7];
        gd7(Wv + e * 64, acc_s, dgrp, o7);
        if (dgrp == 0) {
#pragma unroll
            for (int s = 0; s < 7; ++s) upd_s[s * 64 + e] = o7[s] * psr[s];
        }
    }
    __syncthreads();

    // ---- C: GRU gate pre-activations (384 rows, 6 per warp) ----
    for (int rbv = warp * 4; rbv < 384; rbv += 64) {
        int row = rbv + rowgrp;
        bool ih = row < 192;
        int k = ih ? row : row - 192;
        const float* w = (ih ? W_ih : W_hh) + k * 64;
        const float* v = ih ? upd_s : hprev_s;
        float o7[7];
        gd7(w, v, dgrp, o7);
        if (dgrp == 0) {
            float* dst = ih ? gi_s : gh_s;
#pragma unroll
            for (int s = 0; s < 7; ++s) dst[s * 192 + k] = o7[s];
        }
    }
    __syncthreads();

    // ---- GRU gates ----
    for (int o = tid; o < SD; o += NT) {
        int s = o >> 6, d = o & 63;
        int base = s * 192 + d;
        float r = sigf((gi_s[base]       + b_ih[d])       + (gh_s[base]       + b_hh[d]));
        float z = sigf((gi_s[base + 64]  + b_ih[64 + d])  + (gh_s[base + 64]  + b_hh[64 + d]));
        float n = tanhf((gi_s[base + 128] + b_ih[128 + d]) + r * (gh_s[base + 128] + b_hh[128 + d]));
        h_s[o] = (1.f - z) * n + z * hprev_s[o];
    }
    __syncthreads();

    // ---- D: LN(h) with ln_mlp ----
    ln7(h_s, mx_s, lmg, lmb, warp, lane);
    __syncthreads();

    // ---- E: m1 = relu(mx @ w1^T + b1)  (128 rows, 2 per warp) ----
    for (int rbv = warp * 4; rbv < 128; rbv += 64) {
        int j = rbv + rowgrp;
        float o7[7];
        gd7(w1 + j * 64, mx_s, dgrp, o7);
        if (dgrp == 0) {
#pragma unroll
            for (int s = 0; s < 7; ++s) m1_s[s * 128 + j] = fmaxf(o7[s] + b1[j], 0.f);
        }
    }
    __syncthreads();

    // ---- F: slots = h + m1 @ w2^T + b2  (64 rows, one shot) ----
    {
        int d = warp * 4 + rowgrp;
        float o7[7];
        gd7_128(w2 + d * 128, m1_s, dgrp, o7);
        if (dgrp == 0) {
#pragma unroll
            for (int s = 0; s < 7; ++s) {
                float val = h_s[s * 64 + d] + o7[s] + b2[d];
                slot_s[s * 64 + d] = val;
                g_slots[b * SD + s * 64 + d] = val;
                out[b * SD + s * 64 + d] = val;
            }
        }
    }
    __syncthreads();

    // ---- G: next-iteration qt ----
    ln7(slot_s, mx_s, lsg, lsb, warp, lane);
    __syncthreads();
    qt_phase(b, tid, warp, rowgrp, dgrp, mx_s, q_s, Wq, Wk);
}

// ===========================================================================
// Slot init (reparameterized sampling) and initial qt.
// ===========================================================================
__global__ void __launch_bounds__(64)
init_slots_kernel(const float* __restrict__ nbg, const float* __restrict__ nfg,
                  const float* __restrict__ bgmu, const float* __restrict__ bgls,
                  const float* __restrict__ mu,   const float* __restrict__ ls)
{
    int b = blockIdx.x, d = threadIdx.x;
    g_slots[b * SD + d] = bgmu[d] + expf(bgls[d]) * nbg[b * 64 + d];
#pragma unroll
    for (int s = 1; s < 7; ++s)
        g_slots[b * SD + s * 64 + d] = mu[d] + expf(ls[d]) * nfg[(b * 6 + s - 1) * 64 + d];
}

__global__ void __launch_bounds__(NT)
qt_kernel(const float* __restrict__ lsg, const float* __restrict__ lsb,
          const float* __restrict__ Wq, const float* __restrict__ Wk)
{
    __shared__ float slot_s[SD], sln_s[SD], q_s[SD];
    const int b = blockIdx.x, tid = threadIdx.x;
    const int warp = tid >> 5, lane = tid & 31;
    const int rowgrp = lane >> 3, dgrp = lane & 7;

    for (int i = tid; i < SD; i += NT) slot_s[i] = g_slots[b * SD + i];
    __syncthreads();
    ln7(slot_s, sln_s, lsg, lsb, warp, lane);
    __syncthreads();
    qt_phase(b, tid, warp, rowgrp, dgrp, sln_s, q_s, Wq, Wk);
}

// ===========================================================================
extern "C" void kernel_launch(void* const* d_in, const int* in_sizes, int n_in,
                              void* d_out, int out_size)
{
    const float* inputs   = (const float*)d_in[0];
    const float* noise_bg = (const float*)d_in[1];
    const float* noise_fg = (const float*)d_in[2];
    const float* ln_in_g  = (const float*)d_in[3];
    const float* ln_in_b  = (const float*)d_in[4];
    const float* ln_sl_g  = (const float*)d_in[5];
    const float* ln_sl_b  = (const float*)d_in[6];
    const float* ln_ml_g  = (const float*)d_in[7];
    const float* ln_ml_b  = (const float*)d_in[8];
    const float* Wq       = (const float*)d_in[9];
    const float* Wk       = (const float*)d_in[10];
    const float* Wv       = (const float*)d_in[11];
    const float* W_ih     = (const float*)d_in[12];
    const float* W_hh     = (const float*)d_in[13];
    const float* b_ih     = (const float*)d_in[14];
    const float* b_hh     = (const float*)d_in[15];
    const float* mlp_w1   = (const float*)d_in[16];
    const float* mlp_b1   = (const float*)d_in[17];
    const float* mlp_w2   = (const float*)d_in[18];
    const float* mlp_b2   = (const float*)d_in[19];
    const float* s_bg_mu  = (const float*)d_in[20];
    const float* s_bg_ls  = (const float*)d_in[21];
    const float* s_mu     = (const float*)d_in[22];
    const float* s_ls     = (const float*)d_in[23];
    float* out = (float*)d_out;

    init_slots_kernel<<<BN, 64>>>(noise_bg, noise_fg, s_bg_mu, s_bg_ls, s_mu, s_ls);
    qt_kernel<<<BN, NT>>>(ln_sl_g, ln_sl_b, Wq, Wk);
    for (int it = 0; it < 3; ++it) {
        attn_kernel<<<dim3(CH, BN), 128>>>(inputs, ln_in_g, ln_in_b);
        update_kernel<<<BN, NT>>>(Wv, W_ih, W_hh, b_ih, b_hh,
                                  ln_ml_g, ln_ml_b, mlp_w1, mlp_b1, mlp_w2, mlp_b2,
                                  ln_sl_g, ln_sl_b, Wq, Wk, out);
    }
}